// round 4
// baseline (speedup 1.0000x reference)
#include <cuda_runtime.h>
#include <math.h>

#define Bb 4
#define Tt 2048
#define Ee 1024
#define Hh 64
#define ROWS (Bb*Tt)

// Scratch for projected Q/K/V (allocation-free rule: device globals)
__device__ float g_q[ROWS*Hh];
__device__ float g_k[ROWS*Hh];
__device__ float g_v[ROWS*Hh];

// ---------------------------------------------------------------------------
// Kernel 1: fused QKV projection. grid = (128 row-tiles, 3 matrices), 256 thr.
// Each block computes a 64x64 output tile of one of Q/K/V.
// ---------------------------------------------------------------------------
__global__ __launch_bounds__(256) void qkv_gemm(
    const float* __restrict__ x,
    const float* __restrict__ Wq, const float* __restrict__ bq,
    const float* __restrict__ Wk, const float* __restrict__ bk,
    const float* __restrict__ Wv, const float* __restrict__ bv)
{
    __shared__ float As[64][17];   // x tile, padded against bank conflicts
    __shared__ float Bs[16][64];   // W tile

    const int which = blockIdx.y;
    const float* __restrict__ W    = (which == 0) ? Wq : (which == 1) ? Wk : Wv;
    const float* __restrict__ bias = (which == 0) ? bq : (which == 1) ? bk : bv;
    float* __restrict__ outp       = (which == 0) ? g_q : (which == 1) ? g_k : g_v;

    const int row0 = blockIdx.x * 64;
    const int tid = threadIdx.x;
    const int tx = tid & 15;       // 0..15  (cols /4)
    const int ty = tid >> 4;       // 0..15  (rows /4)

    float c[4][4] = {};

    for (int k0 = 0; k0 < Ee; k0 += 16) {
        // load 64x16 x-tile
        {
            int r = tid >> 2, kq = (tid & 3) * 4;
            float4 v = *(const float4*)(x + (size_t)(row0 + r) * Ee + k0 + kq);
            As[r][kq + 0] = v.x; As[r][kq + 1] = v.y;
            As[r][kq + 2] = v.z; As[r][kq + 3] = v.w;
        }
        // load 16x64 W-tile
        {
            int kr = tid >> 4, c4 = (tid & 15) * 4;
            *(float4*)&Bs[kr][c4] = *(const float4*)(W + (size_t)(k0 + kr) * Hh + c4);
        }
        __syncthreads();

        #pragma unroll
        for (int k = 0; k < 16; ++k) {
            float a0 = As[ty * 4 + 0][k];
            float a1 = As[ty * 4 + 1][k];
            float a2 = As[ty * 4 + 2][k];
            float a3 = As[ty * 4 + 3][k];
            float4 bb = *(float4*)&Bs[k][tx * 4];
            c[0][0] = fmaf(a0, bb.x, c[0][0]); c[0][1] = fmaf(a0, bb.y, c[0][1]);
            c[0][2] = fmaf(a0, bb.z, c[0][2]); c[0][3] = fmaf(a0, bb.w, c[0][3]);
            c[1][0] = fmaf(a1, bb.x, c[1][0]); c[1][1] = fmaf(a1, bb.y, c[1][1]);
            c[1][2] = fmaf(a1, bb.z, c[1][2]); c[1][3] = fmaf(a1, bb.w, c[1][3]);
            c[2][0] = fmaf(a2, bb.x, c[2][0]); c[2][1] = fmaf(a2, bb.y, c[2][1]);
            c[2][2] = fmaf(a2, bb.z, c[2][2]); c[2][3] = fmaf(a2, bb.w, c[2][3]);
            c[3][0] = fmaf(a3, bb.x, c[3][0]); c[3][1] = fmaf(a3, bb.y, c[3][1]);
            c[3][2] = fmaf(a3, bb.z, c[3][2]); c[3][3] = fmaf(a3, bb.w, c[3][3]);
        }
        __syncthreads();
    }

    float4 bb = *(const float4*)(bias + tx * 4);
    #pragma unroll
    for (int i = 0; i < 4; ++i) {
        float4 o;
        o.x = c[i][0] + bb.x; o.y = c[i][1] + bb.y;
        o.z = c[i][2] + bb.z; o.w = c[i][3] + bb.w;
        *(float4*)(outp + (size_t)(row0 + ty * 4 + i) * Hh + tx * 4) = o;
    }
}

// ---------------------------------------------------------------------------
// Kernel 2: causal flash attention, fp32, LOAD-BALANCED.
// 64 q-tiles of 32 queries per batch; block p handles the pair (p, 63-p)
// => every block does exactly 33 key-tile units of work (no tail-block skew).
// grid = (32 pairs, 4 batches), 256 threads = 32 queries x 8 key-slices.
// Warp = 32 lanes of one slice => K/V smem row reads are pure broadcast.
// ---------------------------------------------------------------------------
__global__ __launch_bounds__(256) void attn_kernel(float* __restrict__ out)
{
    __shared__ float sbuf[8192];          // Ks(4096 f) | Vs(4096 f); aliased accS
    __shared__ float msm[256], lsm[256], lgs[32];
    float* Ks = sbuf;
    float* Vs = sbuf + 4096;
    float* accS = sbuf;                   // 32 rows x pitch 68 = 2176 floats

    const int tidx  = threadIdx.x;
    const int qi    = tidx & 31;          // query within 32-row tile
    const int slice = tidx >> 5;          // 0..7 key-slice
    const int pair  = blockIdx.x;         // 0..31
    const int b     = blockIdx.y;

    const float* __restrict__ kb = g_k + ((size_t)(b * Tt)) * Hh;
    const float* __restrict__ vb = g_v + ((size_t)(b * Tt)) * Hh;

    #pragma unroll 1
    for (int half = 0; half < 2; ++half) {
        const int qt  = (half == 0) ? pair : (63 - pair);  // 32-query tile id
        const int qg  = qt * 32 + qi;                      // global query idx
        const int nkt = qt / 2 + 1;                        // 64-key tiles needed

        const float* __restrict__ qrow = g_q + ((size_t)(b * Tt + qg)) * Hh;
        float4 q4[16];
        #pragma unroll
        for (int i = 0; i < 16; ++i) q4[i] = ((const float4*)qrow)[i];

        float4 a4[16];
        #pragma unroll
        for (int i = 0; i < 16; ++i) a4[i] = make_float4(0.f, 0.f, 0.f, 0.f);
        float m = -INFINITY, l = 0.f;

        for (int t0 = 0; t0 < nkt; ++t0) {
            __syncthreads();              // prior use of sbuf complete
            const float4* ksrc = (const float4*)(kb + (size_t)t0 * 64 * Hh);
            const float4* vsrc = (const float4*)(vb + (size_t)t0 * 64 * Hh);
            #pragma unroll
            for (int i = 0; i < 4; ++i) {
                ((float4*)Ks)[tidx + i * 256] = ksrc[tidx + i * 256];
                ((float4*)Vs)[tidx + i * 256] = vsrc[tidx + i * 256];
            }
            __syncthreads();

            float sloc[8];
            float tmax = -INFINITY;
            #pragma unroll
            for (int jj = 0; jj < 8; ++jj) {
                int j = jj * 8 + slice;
                const float4* kr = (const float4*)(Ks + j * Hh);
                float sx = 0.f, sy = 0.f, sz = 0.f, sw = 0.f;
                #pragma unroll
                for (int d = 0; d < 16; ++d) {
                    float4 kv = kr[d];
                    sx = fmaf(q4[d].x, kv.x, sx);
                    sy = fmaf(q4[d].y, kv.y, sy);
                    sz = fmaf(q4[d].z, kv.z, sz);
                    sw = fmaf(q4[d].w, kv.w, sw);
                }
                float s = ((sx + sy) + (sz + sw)) * 8.0f;   // scale = sqrt(64)
                if (t0 * 64 + j > qg) s = -INFINITY;        // causal mask
                tmax = fmaxf(tmax, s);
                sloc[jj] = s;
            }

            float mn = fmaxf(m, tmax);
            if (mn != -INFINITY) {                 // no syncs inside: divergence OK
                float corr = __expf(m - mn);       // m==-inf -> 0
                m = mn;
                l *= corr;
                #pragma unroll
                for (int i = 0; i < 16; ++i) {
                    a4[i].x *= corr; a4[i].y *= corr;
                    a4[i].z *= corr; a4[i].w *= corr;
                }
                #pragma unroll
                for (int jj = 0; jj < 8; ++jj) {
                    float p = __expf(sloc[jj] - mn);   // masked -> 0
                    l += p;
                    const float4* vr = (const float4*)(Vs + (jj * 8 + slice) * Hh);
                    #pragma unroll
                    for (int d = 0; d < 16; ++d) {
                        float4 vv = vr[d];
                        a4[d].x = fmaf(p, vv.x, a4[d].x);
                        a4[d].y = fmaf(p, vv.y, a4[d].y);
                        a4[d].z = fmaf(p, vv.z, a4[d].z);
                        a4[d].w = fmaf(p, vv.w, a4[d].w);
                    }
                }
            }
        }

        // ---- merge 8 slices per query (associative softmax merge) ----
        __syncthreads();
        msm[slice * 32 + qi] = m;
        lsm[slice * 32 + qi] = l;
        __syncthreads();

        float mg = -INFINITY;
        #pragma unroll
        for (int s2 = 0; s2 < 8; ++s2) mg = fmaxf(mg, msm[s2 * 32 + qi]);
        float lg = 0.f;
        #pragma unroll
        for (int s2 = 0; s2 < 8; ++s2)
            lg += lsm[s2 * 32 + qi] * __expf(msm[s2 * 32 + qi] - mg);
        float w = __expf(m - mg);               // this slice's weight (0 if m=-inf)
        if (slice == 0) lgs[qi] = lg;

        float* arow = accS + qi * 68;           // pitch 68 floats
        for (int r = 0; r < 8; ++r) {
            __syncthreads();
            if (slice == r) {
                #pragma unroll
                for (int d = 0; d < 16; ++d) {
                    float4 add;
                    add.x = w * a4[d].x; add.y = w * a4[d].y;
                    add.z = w * a4[d].z; add.w = w * a4[d].w;
                    if (r == 0) {
                        ((float4*)arow)[d] = add;
                    } else {
                        float4 cur = ((float4*)arow)[d];
                        cur.x += add.x; cur.y += add.y;
                        cur.z += add.z; cur.w += add.w;
                        ((float4*)arow)[d] = cur;
                    }
                }
            }
        }
        __syncthreads();

        float* op = out + ((size_t)(b * Tt + qt * 32)) * Hh;
        #pragma unroll
        for (int i = 0; i < 8; ++i) {
            int idx = i * 256 + tidx;           // 0..2047, coalesced stores
            int row = idx >> 6, d = idx & 63;
            op[idx] = accS[row * 68 + d] * __fdividef(1.0f, lgs[row]);
        }
        // next half begins with __syncthreads() before touching sbuf again
    }
}

extern "C" void kernel_launch(void* const* d_in, const int* in_sizes, int n_in,
                              void* d_out, int out_size)
{
    const float* x  = (const float*)d_in[0];
    const float* Wq = (const float*)d_in[1];
    const float* bq = (const float*)d_in[2];
    const float* Wk = (const float*)d_in[3];
    const float* bk = (const float*)d_in[4];
    const float* Wv = (const float*)d_in[5];
    const float* bv = (const float*)d_in[6];
    float* out = (float*)d_out;

    qkv_gemm<<<dim3(128, 3), 256>>>(x, Wq, bq, Wk, bk, Wv, bv);
    attn_kernel<<<dim3(32, 4), 256>>>(out);
}